// round 3
// baseline (speedup 1.0000x reference)
#include <cuda_runtime.h>
#include <math.h>

#define NBATCH   4096
#define MDIM     327
#define NDIM     800
#define NLAYERS  9
#define NB       (4096*800)
#define IMGH     20
#define IMGW     40

// ---------------- device scratch (static, allocation-free) ----------------
__device__ float g_PhiTPhi[NDIM*NDIM];     // W^T W        [800,800]
__device__ float g_PhiTb[NB];              // y @ W        [4096,800]
__device__ float g_hatx[NB];
__device__ float g_X[2*NB];
__device__ float g_Z[2*NB];
__device__ float g_L[2*NB];
__device__ float g_wT2f[32*9*32];          // [ci][tap][co] transposed conv2_forward
__device__ float g_wT1b[32*9*32];          // [ci][tap][co] transposed conv1_backward

// ---------------- weight transpose: [co][ci][t] -> [ci][t][co] ----------------
__global__ void wtransform_kernel(const float* __restrict__ c2f,
                                  const float* __restrict__ c1b) {
    int j = blockIdx.x * blockDim.x + threadIdx.x;
    if (j < 9216) {
        int co = j / 288, r = j % 288, ci = r / 9, t = r % 9;
        g_wT2f[ci*288 + t*32 + co] = c2f[j];
        g_wT1b[ci*288 + t*32 + co] = c1b[j];
    }
}

// ---------------- PhiTPhi = W^T W  (C[800,800], W[327,800]) ----------------
__global__ void phitphi_kernel(const float* __restrict__ W) {
    __shared__ float sI[32][17];
    __shared__ float sJ[32][17];
    int tx = threadIdx.x, ty = threadIdx.y;
    int tid = ty*16 + tx;
    int i0 = blockIdx.y*16, j0 = blockIdx.x*16;
    float acc = 0.f;
    for (int m0 = 0; m0 < MDIM; m0 += 32) {
        #pragma unroll
        for (int l = 0; l < 2; l++) {
            int e = tid + l*256;
            int mm = e >> 4, c = e & 15;
            float vi = 0.f, vj = 0.f;
            if (m0 + mm < MDIM) {
                vi = W[(m0+mm)*NDIM + i0 + c];
                vj = W[(m0+mm)*NDIM + j0 + c];
            }
            sI[mm][c] = vi;
            sJ[mm][c] = vj;
        }
        __syncthreads();
        #pragma unroll
        for (int mm = 0; mm < 32; mm++)
            acc += sI[mm][ty] * sJ[mm][tx];
        __syncthreads();
    }
    g_PhiTPhi[(i0+ty)*NDIM + (j0+tx)] = acc;
}

// ---------------- Wloss = W W^T - I  -> d_out tail ----------------
__global__ void wloss_kernel(const float* __restrict__ W, float* __restrict__ out) {
    __shared__ float sA[16][33];
    __shared__ float sB[16][33];
    int tx = threadIdx.x, ty = threadIdx.y;
    int tid = ty*16 + tx;
    int i0 = blockIdx.y*16, j0 = blockIdx.x*16;
    float acc = 0.f;
    for (int n0 = 0; n0 < NDIM; n0 += 32) {
        #pragma unroll
        for (int l = 0; l < 2; l++) {
            int e = tid + l*256;
            int r = e >> 5, c = e & 31;
            float va = 0.f, vb = 0.f;
            if (i0 + r < MDIM) va = W[(i0+r)*NDIM + n0 + c];
            if (j0 + r < MDIM) vb = W[(j0+r)*NDIM + n0 + c];
            sA[r][c] = va;
            sB[r][c] = vb;
        }
        __syncthreads();
        #pragma unroll
        for (int c = 0; c < 32; c++)
            acc += sA[ty][c] * sB[tx][c];
        __syncthreads();
    }
    int i = i0 + ty, j = j0 + tx;
    if (i < MDIM && j < MDIM)
        out[i*MDIM + j] = acc - (i == j ? 1.f : 0.f);
}

// ---------------- generic 64x64 tiled GEMM + fused X-update epilogue ----------------
// mode 0: C = A@B          mode 1: C = hx + h*(PTB - A@B + b1*(Z - hx) - L)
__global__ void gemm_kernel(const float* __restrict__ A, const float* __restrict__ B,
                            float* __restrict__ C, int Mr, int Nc, int Kd, int mode,
                            const float* __restrict__ PTB, const float* __restrict__ HX,
                            const float* __restrict__ Zg, const float* __restrict__ Lg,
                            const float* __restrict__ hArr, const float* __restrict__ b1Arr,
                            int layer, int useZL) {
    __shared__ float As[16][68];
    __shared__ float Bs[16][68];
    int tx = threadIdx.x, ty = threadIdx.y;
    int tid = ty*16 + tx;
    int row0 = blockIdx.y*64, col0 = blockIdx.x*64;
    float acc[4][4];
    #pragma unroll
    for (int i = 0; i < 4; i++)
        #pragma unroll
        for (int j = 0; j < 4; j++) acc[i][j] = 0.f;

    for (int k0 = 0; k0 < Kd; k0 += 16) {
        #pragma unroll
        for (int l = 0; l < 4; l++) {
            int e = tid + l*256;
            int kk = e & 15, mm = e >> 4;
            float av = 0.f;
            int gr = row0 + mm, gk = k0 + kk;
            if (gr < Mr && gk < Kd) av = A[(size_t)gr*Kd + gk];
            As[kk][mm] = av;
            int nn = e & 63, kb = e >> 6;
            float bv = 0.f;
            int gc = col0 + nn, gk2 = k0 + kb;
            if (gc < Nc && gk2 < Kd) bv = B[(size_t)gk2*Nc + gc];
            Bs[kb][nn] = bv;
        }
        __syncthreads();
        #pragma unroll
        for (int kk = 0; kk < 16; kk++) {
            float4 a = *(const float4*)&As[kk][ty*4];
            float4 b = *(const float4*)&Bs[kk][tx*4];
            float ar[4] = {a.x, a.y, a.z, a.w};
            float br[4] = {b.x, b.y, b.z, b.w};
            #pragma unroll
            for (int i = 0; i < 4; i++)
                #pragma unroll
                for (int j = 0; j < 4; j++)
                    acc[i][j] += ar[i]*br[j];
        }
        __syncthreads();
    }
    float hv = 0.f, b1 = 0.f;
    if (mode == 1) { hv = hArr[layer]; b1 = b1Arr[layer]; }
    #pragma unroll
    for (int i = 0; i < 4; i++) {
        int rr = row0 + ty*4 + i;
        if (rr >= Mr) continue;
        #pragma unroll
        for (int j = 0; j < 4; j++) {
            int cc = col0 + tx*4 + j;
            if (cc >= Nc) continue;
            size_t idx = (size_t)rr*Nc + cc;
            if (mode == 0) {
                C[idx] = acc[i][j];
            } else {
                float hx = HX[idx];
                float zt = useZL ? Zg[idx] : 0.f;
                float lt = useZL ? Lg[idx] : 0.f;
                C[idx] = hx + hv*(PTB[idx] - acc[i][j] + b1*(zt - hx) - lt);
            }
        }
    }
}

// ---------------- elementwise helpers ----------------
__global__ void xlayer0_kernel(const float* __restrict__ ptb, float* __restrict__ out,
                               const float* __restrict__ hArr) {
    int i = blockIdx.x*blockDim.x + threadIdx.x;
    if (i < NB) out[i] = hArr[0]*ptb[i];
}

__global__ void hatx_kernel(const float* __restrict__ Xc, const float* __restrict__ Xp,
                            float* __restrict__ out, const float* __restrict__ txArr,
                            int layer, int usePrev) {
    int i = blockIdx.x*blockDim.x + threadIdx.x;
    if (i < NB) {
        float tx = txArr[layer];
        float v = (1.f + tx)*Xc[i];
        if (usePrev) v -= tx*Xp[i];
        out[i] = v;
    }
}

// ---------------- fused conv block: one CTA per image, all 6 convs in smem ----------------
// smem: zin padded [22][42] (928 pad), A[32*800], B[32*800], w1f[288], w2b[288]
#define SMEM_FLOATS (928 + 25600 + 25600 + 288 + 288)
#define SMEM_BYTES  (SMEM_FLOATS*4)

template<bool SOFT, bool RELU>
__device__ __forceinline__ void conv32(const float* __restrict__ inb,
                                       float* __restrict__ outb,
                                       const float* __restrict__ wT,
                                       float sthr, int tid) {
    const int DT[9] = {-41,-40,-39,-1,0,1,39,40,41};
    int pk[4]; unsigned mk[4];
    #pragma unroll
    for (int k = 0; k < 4; k++) {
        int p = tid + k*256;
        pk[k] = p;
        int y = p/40, x = p%40;
        unsigned m = 0;
        #pragma unroll
        for (int t = 0; t < 9; t++) {
            int yy = y + t/3 - 1, xx = x + t%3 - 1;
            if (p < 800 && yy >= 0 && yy < IMGH && xx >= 0 && xx < IMGW) m |= 1u << t;
        }
        mk[k] = m;
    }
    for (int cb = 0; cb < 4; cb++) {
        float acc[8][4];
        #pragma unroll
        for (int c = 0; c < 8; c++)
            #pragma unroll
            for (int k = 0; k < 4; k++) acc[c][k] = 0.f;
        for (int ci = 0; ci < 32; ci++) {
            const float* inc = inb + ci*800;
            const float* wci = wT + ci*288 + cb*8;
            #pragma unroll
            for (int t = 0; t < 9; t++) {
                float4 wA = *(const float4*)(wci + t*32);
                float4 wB = *(const float4*)(wci + t*32 + 4);
                #pragma unroll
                for (int k = 0; k < 4; k++) {
                    if (mk[k] & (1u << t)) {
                        float v = inc[pk[k] + DT[t]];
                        if (SOFT) {
                            float a1 = fabsf(v) - sthr;
                            v = a1 > 0.f ? copysignf(a1, v) : 0.f;
                        }
                        acc[0][k] += wA.x*v; acc[1][k] += wA.y*v;
                        acc[2][k] += wA.z*v; acc[3][k] += wA.w*v;
                        acc[4][k] += wB.x*v; acc[5][k] += wB.y*v;
                        acc[6][k] += wB.z*v; acc[7][k] += wB.w*v;
                    }
                }
            }
        }
        #pragma unroll
        for (int k = 0; k < 4; k++) {
            if (pk[k] < 800) {
                #pragma unroll
                for (int co = 0; co < 8; co++) {
                    float o = acc[co][k];
                    if (RELU) o = fmaxf(o, 0.f);
                    outb[(cb*8 + co)*800 + pk[k]] = o;
                }
            }
        }
    }
}

__global__ void __launch_bounds__(256)
conv_block_kernel(const float* __restrict__ Xn,
                  const float* __restrict__ Zc, const float* __restrict__ Zp,
                  const float* __restrict__ Lc, const float* __restrict__ Lp,
                  float* __restrict__ Znew, float* __restrict__ Lnew,
                  float* __restrict__ outZ, float* __restrict__ outSym,
                  const float* __restrict__ w1f, const float* __restrict__ w2b,
                  const float* __restrict__ hArr, const float* __restrict__ b1Arr,
                  const float* __restrict__ b2Arr, const float* __restrict__ tzArr,
                  const float* __restrict__ tLArr, const float* __restrict__ thrArr,
                  int layer) {
    extern __shared__ float sm[];
    float* zin = sm;                 // 928 (22*42 = 924 used)
    float* Ab  = sm + 928;           // 25600
    float* Bb  = Ab + 25600;         // 25600
    float* w1s = Bb + 25600;         // 288
    float* w2s = w1s + 288;          // 288

    const int DT[9] = {-41,-40,-39,-1,0,1,39,40,41};
    int tid = threadIdx.x;
    int b = blockIdx.x;
    int base = b*800;

    float hv  = hArr[layer], b1 = b1Arr[layer], b2 = b2Arr[layer];
    float tz  = tzArr[layer], tL = tLArr[layer];
    float thr = fabsf(thrArr[layer]);
    bool useZc = (layer >= 1), useZp = (layer >= 2);
    bool useLg = (layer >= 2), useLc = (layer >= 1), useLp = (layer >= 2);

    for (int i = tid; i < 288; i += 256) { w1s[i] = w1f[i]; w2s[i] = w2b[i]; }
    for (int i = tid; i < 924; i += 256) zin[i] = 0.f;
    __syncthreads();

    // z_flat = hatz + h*(L + b2*(Xn - hatz)) into padded zin
    for (int p = tid; p < 800; p += 256) {
        int idx = base + p;
        float xn = Xn[idx];
        float hz = 0.f;
        if (useZc) hz = (1.f + tz)*Zc[idx];
        if (useZp) hz -= tz*Zp[idx];
        float lt = useLg ? Lc[idx] : 0.f;
        float z = hz + hv*(lt + b2*(xn - hz));
        zin[(p/40 + 1)*42 + (p%40) + 1] = z;
    }
    __syncthreads();

    // conv1_forward (1->32) + relu -> Ab
    for (int p = tid; p < 800; p += 256) {
        int y = p/40, x = p%40;
        float z9[9];
        #pragma unroll
        for (int t = 0; t < 9; t++) z9[t] = zin[(y + t/3)*42 + x + t%3];
        for (int co = 0; co < 32; co++) {
            float s = 0.f;
            #pragma unroll
            for (int t = 0; t < 9; t++) s += w1s[co*9 + t]*z9[t];
            Ab[co*800 + p] = fmaxf(s, 0.f);
        }
    }
    __syncthreads();

    // x_fwd = conv2_forward(Ab) -> Bb
    conv32<false, false>(Ab, Bb, g_wT2f, 0.f, tid);
    __syncthreads();

    // relu(conv1_backward(soft(x_fwd))) -> Ab
    conv32<true, true>(Bb, Ab, g_wT1b, thr, tid);
    __syncthreads();

    // x_back = conv2_backward(Ab); Z_new, L_new updates
    for (int p = tid; p < 800; p += 256) {
        int y = p/40, x = p%40;
        unsigned m = 0;
        #pragma unroll
        for (int t = 0; t < 9; t++) {
            int yy = y + t/3 - 1, xx = x + t%3 - 1;
            if (yy >= 0 && yy < IMGH && xx >= 0 && xx < IMGW) m |= 1u << t;
        }
        float acc = 0.f;
        for (int ci = 0; ci < 32; ci++) {
            const float* ac = Ab + ci*800;
            const float* wc = w2s + ci*9;
            #pragma unroll
            for (int t = 0; t < 9; t++)
                if (m & (1u << t)) acc += wc[t]*ac[p + DT[t]];
        }
        int idx = base + p;
        float zn = acc;
        Znew[idx] = zn;
        outZ[idx] = zn;
        float xn = Xn[idx];
        float hl = 0.f;
        if (useLc) hl = (1.f + tL)*Lc[idx];
        if (useLp) hl -= tL*Lp[idx];
        Lnew[idx] = hl + hv*b1*(xn - zn);
    }
    __syncthreads();

    // relu(conv1_backward(x_fwd)) -> Ab
    conv32<false, true>(Bb, Ab, g_wT1b, 0.f, tid);
    __syncthreads();

    // x_sym = conv2_backward(Ab); sym = x_sym - z_in
    for (int p = tid; p < 800; p += 256) {
        int y = p/40, x = p%40;
        unsigned m = 0;
        #pragma unroll
        for (int t = 0; t < 9; t++) {
            int yy = y + t/3 - 1, xx = x + t%3 - 1;
            if (yy >= 0 && yy < IMGH && xx >= 0 && xx < IMGW) m |= 1u << t;
        }
        float acc = 0.f;
        for (int ci = 0; ci < 32; ci++) {
            const float* ac = Ab + ci*800;
            const float* wc = w2s + ci*9;
            #pragma unroll
            for (int t = 0; t < 9; t++)
                if (m & (1u << t)) acc += wc[t]*ac[p + DT[t]];
        }
        outSym[base + p] = acc - zin[(y + 1)*42 + x + 1];
    }
}

// ---------------- launch ----------------
extern "C" void kernel_launch(void* const* d_in, const int* in_sizes, int n_in,
                              void* d_out, int out_size) {
    const float* y   = (const float*)d_in[0];
    const float* W   = (const float*)d_in[2];
    const float* b1  = (const float*)d_in[3];
    const float* b2  = (const float*)d_in[4];
    const float* h   = (const float*)d_in[5];
    const float* thr = (const float*)d_in[6];
    const float* txA = (const float*)d_in[7];
    const float* tzA = (const float*)d_in[8];
    const float* tLA = (const float*)d_in[9];
    const float* c1f = (const float*)d_in[10];
    const float* c2f = (const float*)d_in[11];
    const float* c1b = (const float*)d_in[12];
    const float* c2b = (const float*)d_in[13];
    float* out = (float*)d_out;

    cudaFuncSetAttribute(conv_block_kernel,
                         cudaFuncAttributeMaxDynamicSharedMemorySize, SMEM_BYTES);

    float *pPTP, *pPTB, *pHX, *pX, *pZ, *pL;
    cudaGetSymbolAddress((void**)&pPTP, g_PhiTPhi);
    cudaGetSymbolAddress((void**)&pPTB, g_PhiTb);
    cudaGetSymbolAddress((void**)&pHX,  g_hatx);
    cudaGetSymbolAddress((void**)&pX,   g_X);
    cudaGetSymbolAddress((void**)&pZ,   g_Z);
    cudaGetSymbolAddress((void**)&pL,   g_L);

    // precomputes
    wtransform_kernel<<<36, 256>>>(c2f, c1b);
    phitphi_kernel<<<dim3(50, 50), dim3(16, 16)>>>(W);
    gemm_kernel<<<dim3(13, 64), dim3(16, 16)>>>(y, W, pPTB, NBATCH, NDIM, MDIM, 0,
                                                nullptr, nullptr, nullptr, nullptr,
                                                nullptr, nullptr, 0, 0);
    wloss_kernel<<<dim3(21, 21), dim3(16, 16)>>>(W, out + (size_t)2*NLAYERS*NB);

    for (int i = 0; i < NLAYERS; i++) {
        int cur = i & 1, nxt = (i + 1) & 1;
        if (i == 0) {
            xlayer0_kernel<<<(NB + 255)/256, 256>>>(pPTB, pX + (size_t)nxt*NB, h);
        } else {
            hatx_kernel<<<(NB + 255)/256, 256>>>(pX + (size_t)cur*NB, pX + (size_t)nxt*NB,
                                                 pHX, txA, i, (i >= 2) ? 1 : 0);
            gemm_kernel<<<dim3(13, 64), dim3(16, 16)>>>(pHX, pPTP, pX + (size_t)nxt*NB,
                                                        NBATCH, NDIM, NDIM, 1,
                                                        pPTB, pHX,
                                                        pZ + (size_t)cur*NB,
                                                        pL + (size_t)cur*NB,
                                                        h, b1, i, (i >= 2) ? 1 : 0);
        }
        conv_block_kernel<<<NBATCH, 256, SMEM_BYTES>>>(
            pX + (size_t)nxt*NB,
            pZ + (size_t)cur*NB, pZ + (size_t)nxt*NB,
            pL + (size_t)cur*NB, pL + (size_t)nxt*NB,
            pZ + (size_t)nxt*NB, pL + (size_t)nxt*NB,
            out + (size_t)i*NB,
            out + (size_t)NLAYERS*NB + (size_t)i*NB,
            c1f, c2b, h, b1, b2, tzA, tLA, thr, i);
    }
}

// round 7
// speedup vs baseline: 3.6633x; 3.6633x over previous
#include <cuda_runtime.h>
#include <math.h>

#define NBATCH   4096
#define MDIM     327
#define NDIM     800
#define NLAYERS  9
#define NB       (4096*800)
#define IMGH     20
#define IMGW     40

// ---------------- device scratch (static, allocation-free) ----------------
__device__ float g_PhiTPhi[NDIM*NDIM];     // W^T W        [800,800]
__device__ float g_PhiTb[NB];              // y @ W        [4096,800]
__device__ float g_hatx[NB];
__device__ float g_X[2*NB];
__device__ float g_Z[2*NB];
__device__ float g_L[2*NB];
__device__ float g_wT2f[32*9*32];          // [ci][tap][co] transposed conv2_forward
__device__ float g_wT1b[32*9*32];          // [ci][tap][co] transposed conv1_backward

// ---------------- weight transpose: [co][ci][t] -> [ci][t][co] ----------------
__global__ void wtransform_kernel(const float* __restrict__ c2f,
                                  const float* __restrict__ c1b) {
    int j = blockIdx.x * blockDim.x + threadIdx.x;
    if (j < 9216) {
        int co = j / 288, r = j % 288, ci = r / 9, t = r % 9;
        g_wT2f[ci*288 + t*32 + co] = c2f[j];
        g_wT1b[ci*288 + t*32 + co] = c1b[j];
    }
}

// ---------------- PhiTPhi = W^T W  (C[800,800], W[327,800]) ----------------
__global__ void phitphi_kernel(const float* __restrict__ W) {
    __shared__ float sI[32][17];
    __shared__ float sJ[32][17];
    int tx = threadIdx.x, ty = threadIdx.y;
    int tid = ty*16 + tx;
    int i0 = blockIdx.y*16, j0 = blockIdx.x*16;
    float acc = 0.f;
    for (int m0 = 0; m0 < MDIM; m0 += 32) {
        #pragma unroll
        for (int l = 0; l < 2; l++) {
            int e = tid + l*256;
            int mm = e >> 4, c = e & 15;
            float vi = 0.f, vj = 0.f;
            if (m0 + mm < MDIM) {
                vi = W[(m0+mm)*NDIM + i0 + c];
                vj = W[(m0+mm)*NDIM + j0 + c];
            }
            sI[mm][c] = vi;
            sJ[mm][c] = vj;
        }
        __syncthreads();
        #pragma unroll
        for (int mm = 0; mm < 32; mm++)
            acc += sI[mm][ty] * sJ[mm][tx];
        __syncthreads();
    }
    g_PhiTPhi[(i0+ty)*NDIM + (j0+tx)] = acc;
}

// ---------------- Wloss = W W^T - I  -> d_out tail ----------------
__global__ void wloss_kernel(const float* __restrict__ W, float* __restrict__ out) {
    __shared__ float sA[16][33];
    __shared__ float sB[16][33];
    int tx = threadIdx.x, ty = threadIdx.y;
    int tid = ty*16 + tx;
    int i0 = blockIdx.y*16, j0 = blockIdx.x*16;
    float acc = 0.f;
    for (int n0 = 0; n0 < NDIM; n0 += 32) {
        #pragma unroll
        for (int l = 0; l < 2; l++) {
            int e = tid + l*256;
            int r = e >> 5, c = e & 31;
            float va = 0.f, vb = 0.f;
            if (i0 + r < MDIM) va = W[(i0+r)*NDIM + n0 + c];
            if (j0 + r < MDIM) vb = W[(j0+r)*NDIM + n0 + c];
            sA[r][c] = va;
            sB[r][c] = vb;
        }
        __syncthreads();
        #pragma unroll
        for (int c = 0; c < 32; c++)
            acc += sA[ty][c] * sB[tx][c];
        __syncthreads();
    }
    int i = i0 + ty, j = j0 + tx;
    if (i < MDIM && j < MDIM)
        out[i*MDIM + j] = acc - (i == j ? 1.f : 0.f);
}

// ---------------- generic 64x64 tiled GEMM + fused X-update epilogue ----------------
// mode 0: C = A@B          mode 1: C = hx + h*(PTB - A@B + b1*(Z - hx) - L)
__global__ void gemm_kernel(const float* __restrict__ A, const float* __restrict__ B,
                            float* __restrict__ C, int Mr, int Nc, int Kd, int mode,
                            const float* __restrict__ PTB, const float* __restrict__ HX,
                            const float* __restrict__ Zg, const float* __restrict__ Lg,
                            const float* __restrict__ hArr, const float* __restrict__ b1Arr,
                            int layer, int useZL) {
    __shared__ float As[16][68];
    __shared__ float Bs[16][68];
    int tx = threadIdx.x, ty = threadIdx.y;
    int tid = ty*16 + tx;
    int row0 = blockIdx.y*64, col0 = blockIdx.x*64;
    float acc[4][4];
    #pragma unroll
    for (int i = 0; i < 4; i++)
        #pragma unroll
        for (int j = 0; j < 4; j++) acc[i][j] = 0.f;

    for (int k0 = 0; k0 < Kd; k0 += 16) {
        #pragma unroll
        for (int l = 0; l < 4; l++) {
            int e = tid + l*256;
            int kk = e & 15, mm = e >> 4;
            float av = 0.f;
            int gr = row0 + mm, gk = k0 + kk;
            if (gr < Mr && gk < Kd) av = A[(size_t)gr*Kd + gk];
            As[kk][mm] = av;
            int nn = e & 63, kb = e >> 6;
            float bv = 0.f;
            int gc = col0 + nn, gk2 = k0 + kb;
            if (gc < Nc && gk2 < Kd) bv = B[(size_t)gk2*Nc + gc];
            Bs[kb][nn] = bv;
        }
        __syncthreads();
        #pragma unroll
        for (int kk = 0; kk < 16; kk++) {
            float4 a = *(const float4*)&As[kk][ty*4];
            float4 b = *(const float4*)&Bs[kk][tx*4];
            float ar[4] = {a.x, a.y, a.z, a.w};
            float br[4] = {b.x, b.y, b.z, b.w};
            #pragma unroll
            for (int i = 0; i < 4; i++)
                #pragma unroll
                for (int j = 0; j < 4; j++)
                    acc[i][j] += ar[i]*br[j];
        }
        __syncthreads();
    }
    float hv = 0.f, b1 = 0.f;
    if (mode == 1) { hv = hArr[layer]; b1 = b1Arr[layer]; }
    #pragma unroll
    for (int i = 0; i < 4; i++) {
        int rr = row0 + ty*4 + i;
        if (rr >= Mr) continue;
        #pragma unroll
        for (int j = 0; j < 4; j++) {
            int cc = col0 + tx*4 + j;
            if (cc >= Nc) continue;
            size_t idx = (size_t)rr*Nc + cc;
            if (mode == 0) {
                C[idx] = acc[i][j];
            } else {
                float hx = HX[idx];
                float zt = useZL ? Zg[idx] : 0.f;
                float lt = useZL ? Lg[idx] : 0.f;
                C[idx] = hx + hv*(PTB[idx] - acc[i][j] + b1*(zt - hx) - lt);
            }
        }
    }
}

// ---------------- elementwise helpers ----------------
__global__ void xlayer0_kernel(const float* __restrict__ ptb, float* __restrict__ out,
                               const float* __restrict__ hArr) {
    int i = blockIdx.x*blockDim.x + threadIdx.x;
    if (i < NB) out[i] = hArr[0]*ptb[i];
}

__global__ void hatx_kernel(const float* __restrict__ Xc, const float* __restrict__ Xp,
                            float* __restrict__ out, const float* __restrict__ txArr,
                            int layer, int usePrev) {
    int i = blockIdx.x*blockDim.x + threadIdx.x;
    if (i < NB) {
        float tx = txArr[layer];
        float v = (1.f + tx)*Xc[i];
        if (usePrev) v -= tx*Xp[i];
        out[i] = v;
    }
}

// ---------------- fused conv block ----------------
// Activation buffers are column-padded: per channel 20 rows x 42 cols (cols 0 and
// 41 are permanent zero halos). Channel stride 840. Top/bottom taps guarded by
// per-thread row flags. Each active thread (tid<200) owns 4 consecutive pixels
// in one row: y = tid/10, x0 = (tid%10)*4.
//
// smem floats: zin 924 | Ab 26880 | Bb 26880 | wS 576 | w1s 288 | w2s 288 = 55836
#define SMEM_FLOATS 55836
#define SMEM_BYTES  (SMEM_FLOATS*4)

template<bool SOFT, bool RELU>
__device__ __forceinline__ void conv32p(const float* __restrict__ inb,
                                        float* __restrict__ outb,
                                        const float* __restrict__ wG,
                                        float* __restrict__ wS,
                                        float sthr, int tid) {
    bool act = (tid < 200);
    int y  = tid/10;
    int xq = (tid%10)*4;
    int base = y*42 + xq;                 // padded col of (x0-1)
    bool hasTop = (y > 0), hasBot = (y < 19);

    float acc[32][4];
    #pragma unroll
    for (int co = 0; co < 32; co++)
        #pragma unroll
        for (int k = 0; k < 4; k++) acc[co][k] = 0.f;

    // prefetch weights for ci=0 into wS[0..287]
    if (tid < 72)
        *(float4*)&wS[tid*4] = *(const float4*)&wG[tid*4];
    __syncthreads();

    for (int ci = 0; ci < 32; ci++) {
        const float* wcur = wS + (ci & 1)*288;
        float* wnxt = wS + ((ci + 1) & 1)*288;
        if (ci + 1 < 32 && tid < 72)
            *(float4*)&wnxt[tid*4] = *(const float4*)&wG[(ci+1)*288 + tid*4];

        if (act) {
            const float* p = inb + ci*840 + base;
            float v[18];
            #pragma unroll
            for (int c = 0; c < 6; c++) {
                v[c]      = hasTop ? p[c - 42] : 0.f;
                v[6 + c]  = p[c];
                v[12 + c] = hasBot ? p[c + 42] : 0.f;
            }
            if (SOFT) {
                #pragma unroll
                for (int c = 0; c < 18; c++) {
                    float a1 = fabsf(v[c]) - sthr;
                    v[c] = a1 > 0.f ? copysignf(a1, v[c]) : 0.f;
                }
            }
            #pragma unroll
            for (int t = 0; t < 9; t++) {
                int dy = t/3, dx = t%3;
                #pragma unroll
                for (int cg = 0; cg < 8; cg++) {
                    float4 w = *(const float4*)&wcur[t*32 + cg*4];
                    #pragma unroll
                    for (int k = 0; k < 4; k++) {
                        float vv = v[dy*6 + k + dx];
                        acc[cg*4+0][k] += w.x*vv;
                        acc[cg*4+1][k] += w.y*vv;
                        acc[cg*4+2][k] += w.z*vv;
                        acc[cg*4+3][k] += w.w*vv;
                    }
                }
            }
        }
        __syncthreads();
    }

    if (act) {
        #pragma unroll
        for (int co = 0; co < 32; co++) {
            float* o = outb + co*840 + base + 1;
            #pragma unroll
            for (int k = 0; k < 4; k++) {
                float r = acc[co][k];
                if (RELU) r = fmaxf(r, 0.f);
                o[k] = r;
            }
        }
    }
}

// conv2_backward on a padded 32-ch buffer: 4 output values for this thread's quad
__device__ __forceinline__ void conv2b_quad(const float* __restrict__ inb,
                                            const float* __restrict__ w2s,
                                            float out[4], int tid) {
    int y  = tid/10;
    int xq = (tid%10)*4;
    int base = y*42 + xq;
    bool hasTop = (y > 0), hasBot = (y < 19);
    out[0] = out[1] = out[2] = out[3] = 0.f;
    for (int ci = 0; ci < 32; ci++) {
        const float* p = inb + ci*840 + base;
        float v[18];
        #pragma unroll
        for (int c = 0; c < 6; c++) {
            v[c]      = hasTop ? p[c - 42] : 0.f;
            v[6 + c]  = p[c];
            v[12 + c] = hasBot ? p[c + 42] : 0.f;
        }
        const float* wc = w2s + ci*9;
        #pragma unroll
        for (int t = 0; t < 9; t++) {
            int dy = t/3, dx = t%3;
            float wv = wc[t];
            #pragma unroll
            for (int k = 0; k < 4; k++)
                out[k] += wv * v[dy*6 + k + dx];
        }
    }
}

__global__ void __launch_bounds__(256)
conv_block_kernel(const float* __restrict__ Xn,
                  const float* __restrict__ Zc, const float* __restrict__ Zp,
                  const float* __restrict__ Lc, const float* __restrict__ Lp,
                  float* __restrict__ Znew, float* __restrict__ Lnew,
                  float* __restrict__ outZ, float* __restrict__ outSym,
                  const float* __restrict__ w1f, const float* __restrict__ w2b,
                  const float* __restrict__ hArr, const float* __restrict__ b1Arr,
                  const float* __restrict__ b2Arr, const float* __restrict__ tzArr,
                  const float* __restrict__ tLArr, const float* __restrict__ thrArr,
                  int layer) {
    extern __shared__ float sm[];
    float* zin = sm;                 // 924  (22x42, fully padded, zero halo)
    float* Ab  = sm + 924;           // 26880 (32 x 20x42, zero halo cols)
    float* Bb  = Ab + 26880;         // 26880
    float* wS  = Bb + 26880;         // 576 (double-buffered weight stage)
    float* w1s = wS + 576;           // 288
    float* w2s = w1s + 288;          // 288

    int tid = threadIdx.x;
    int b = blockIdx.x;
    bool act = (tid < 200);
    int y  = tid/10;
    int xq = (tid%10)*4;
    int qidx = b*200 + tid;          // float4 index of this thread's quad

    float hv  = hArr[layer], b1 = b1Arr[layer], b2 = b2Arr[layer];
    float tz  = tzArr[layer], tL = tLArr[layer];
    float thr = fabsf(thrArr[layer]);
    bool useZc = (layer >= 1), useZp = (layer >= 2);
    bool useLg = (layer >= 2), useLc = (layer >= 1), useLp = (layer >= 2);

    // ---- init: weights, zin zero, halo columns of Ab/Bb zero ----
    for (int i = tid; i < 288; i += 256) { w1s[i] = w1f[i]; w2s[i] = w2b[i]; }
    for (int i = tid; i < 924; i += 256) zin[i] = 0.f;
    for (int i = tid; i < 640; i += 256) {          // 32ch * 20 rows
        Ab[i*42] = 0.f; Ab[i*42 + 41] = 0.f;
        Bb[i*42] = 0.f; Bb[i*42 + 41] = 0.f;
    }
    __syncthreads();   // FIX: zin zero-fill must complete before interior z writes
                       // (zero-writer thread != z-writer thread for the same cell)

    // ---- z_flat = hatz + h*(L + b2*(Xn - hatz)) -> padded zin ----
    if (act) {
        float4 xn4 = ((const float4*)Xn)[qidx];
        float4 zc4 = make_float4(0.f,0.f,0.f,0.f);
        float4 zp4 = make_float4(0.f,0.f,0.f,0.f);
        float4 lc4 = make_float4(0.f,0.f,0.f,0.f);
        if (useZc) zc4 = ((const float4*)Zc)[qidx];
        if (useZp) zp4 = ((const float4*)Zp)[qidx];
        if (useLg) lc4 = ((const float4*)Lc)[qidx];
        float xn[4] = {xn4.x, xn4.y, xn4.z, xn4.w};
        float zcv[4] = {zc4.x, zc4.y, zc4.z, zc4.w};
        float zpv[4] = {zp4.x, zp4.y, zp4.z, zp4.w};
        float lcv[4] = {lc4.x, lc4.y, lc4.z, lc4.w};
        float* zrow = zin + (y + 1)*42 + xq + 1;
        #pragma unroll
        for (int k = 0; k < 4; k++) {
            float hz = useZc ? (1.f + tz)*zcv[k] : 0.f;
            if (useZp) hz -= tz*zpv[k];
            float lt = useLg ? lcv[k] : 0.f;
            zrow[k] = hz + hv*(lt + b2*(xn[k] - hz));
        }
    }
    __syncthreads();

    // ---- conv1_forward (1->32) + relu -> Ab ----
    if (act) {
        float v[18];
        #pragma unroll
        for (int c = 0; c < 6; c++) {
            v[c]      = zin[ y     *42 + xq + c];
            v[6 + c]  = zin[(y + 1)*42 + xq + c];
            v[12 + c] = zin[(y + 2)*42 + xq + c];
        }
        #pragma unroll
        for (int co = 0; co < 32; co++) {
            float a0 = 0.f, a1v = 0.f, a2 = 0.f, a3 = 0.f;
            #pragma unroll
            for (int t = 0; t < 9; t++) {
                int dy = t/3, dx = t%3;
                float wv = w1s[co*9 + t];
                a0 += wv*v[dy*6 + 0 + dx];
                a1v+= wv*v[dy*6 + 1 + dx];
                a2 += wv*v[dy*6 + 2 + dx];
                a3 += wv*v[dy*6 + 3 + dx];
            }
            float* o = Ab + co*840 + y*42 + xq + 1;
            o[0] = fmaxf(a0, 0.f); o[1] = fmaxf(a1v, 0.f);
            o[2] = fmaxf(a2, 0.f); o[3] = fmaxf(a3, 0.f);
        }
    }

    // ---- x_fwd = conv2_forward(Ab) -> Bb ----  (internal sync covers Ab writes)
    conv32p<false, false>(Ab, Bb, g_wT2f, wS, 0.f, tid);
    __syncthreads();

    // ---- relu(conv1_backward(soft(x_fwd))) -> Ab ----
    conv32p<true, true>(Bb, Ab, g_wT1b, wS, thr, tid);
    __syncthreads();

    // ---- x_back = conv2_backward(Ab); Z_new, L_new ----
    if (act) {
        float xb[4];
        conv2b_quad(Ab, w2s, xb, tid);
        float4 xn4 = ((const float4*)Xn)[qidx];
        float xn[4] = {xn4.x, xn4.y, xn4.z, xn4.w};
        float4 lc4 = make_float4(0.f,0.f,0.f,0.f);
        float4 lp4 = make_float4(0.f,0.f,0.f,0.f);
        if (useLc) lc4 = ((const float4*)Lc)[qidx];
        if (useLp) lp4 = ((const float4*)Lp)[qidx];
        float lcv[4] = {lc4.x, lc4.y, lc4.z, lc4.w};
        float lpv[4] = {lp4.x, lp4.y, lp4.z, lp4.w};
        float4 zo, lo;
        float zk[4], lk[4];
        #pragma unroll
        for (int k = 0; k < 4; k++) {
            float zn = xb[k];
            zk[k] = zn;
            float hl = useLc ? (1.f + tL)*lcv[k] : 0.f;
            if (useLp) hl -= tL*lpv[k];
            lk[k] = hl + hv*b1*(xn[k] - zn);
        }
        zo = make_float4(zk[0], zk[1], zk[2], zk[3]);
        lo = make_float4(lk[0], lk[1], lk[2], lk[3]);
        ((float4*)Znew)[qidx] = zo;
        ((float4*)outZ)[qidx] = zo;
        ((float4*)Lnew)[qidx] = lo;
    }
    __syncthreads();   // all reads of Ab done before overwrite

    // ---- relu(conv1_backward(x_fwd)) -> Ab ----
    conv32p<false, true>(Bb, Ab, g_wT1b, wS, 0.f, tid);
    __syncthreads();

    // ---- x_sym = conv2_backward(Ab); sym = x_sym - z_in ----
    if (act) {
        float xs[4];
        conv2b_quad(Ab, w2s, xs, tid);
        const float* zrow = zin + (y + 1)*42 + xq + 1;
        float4 so = make_float4(xs[0] - zrow[0], xs[1] - zrow[1],
                                xs[2] - zrow[2], xs[3] - zrow[3]);
        ((float4*)outSym)[qidx] = so;
    }
}

// ---------------- launch ----------------
extern "C" void kernel_launch(void* const* d_in, const int* in_sizes, int n_in,
                              void* d_out, int out_size) {
    const float* y   = (const float*)d_in[0];
    const float* W   = (const float*)d_in[2];
    const float* b1  = (const float*)d_in[3];
    const float* b2  = (const float*)d_in[4];
    const float* h   = (const float*)d_in[5];
    const float* thr = (const float*)d_in[6];
    const float* txA = (const float*)d_in[7];
    const float* tzA = (const float*)d_in[8];
    const float* tLA = (const float*)d_in[9];
    const float* c1f = (const float*)d_in[10];
    const float* c2f = (const float*)d_in[11];
    const float* c1b = (const float*)d_in[12];
    const float* c2b = (const float*)d_in[13];
    float* out = (float*)d_out;

    cudaFuncSetAttribute(conv_block_kernel,
                         cudaFuncAttributeMaxDynamicSharedMemorySize, SMEM_BYTES);

    float *pPTP, *pPTB, *pHX, *pX, *pZ, *pL;
    cudaGetSymbolAddress((void**)&pPTP, g_PhiTPhi);
    cudaGetSymbolAddress((void**)&pPTB, g_PhiTb);
    cudaGetSymbolAddress((void**)&pHX,  g_hatx);
    cudaGetSymbolAddress((void**)&pX,   g_X);
    cudaGetSymbolAddress((void**)&pZ,   g_Z);
    cudaGetSymbolAddress((void**)&pL,   g_L);

    // precomputes
    wtransform_kernel<<<36, 256>>>(c2f, c1b);
    phitphi_kernel<<<dim3(50, 50), dim3(16, 16)>>>(W);
    gemm_kernel<<<dim3(13, 64), dim3(16, 16)>>>(y, W, pPTB, NBATCH, NDIM, MDIM, 0,
                                                nullptr, nullptr, nullptr, nullptr,
                                                nullptr, nullptr, 0, 0);
    wloss_kernel<<<dim3(21, 21), dim3(16, 16)>>>(W, out + (size_t)2*NLAYERS*NB);

    for (int i = 0; i < NLAYERS; i++) {
        int cur = i & 1, nxt = (i + 1) & 1;
        if (i == 0) {
            xlayer0_kernel<<<(NB + 255)/256, 256>>>(pPTB, pX + (size_t)nxt*NB, h);
        } else {
            hatx_kernel<<<(NB + 255)/256, 256>>>(pX + (size_t)cur*NB, pX + (size_t)nxt*NB,
                                                 pHX, txA, i, (i >= 2) ? 1 : 0);
            gemm_kernel<<<dim3(13, 64), dim3(16, 16)>>>(pHX, pPTP, pX + (size_t)nxt*NB,
                                                        NBATCH, NDIM, NDIM, 1,
                                                        pPTB, pHX,
                                                        pZ + (size_t)cur*NB,
                                                        pL + (size_t)cur*NB,
                                                        h, b1, i, (i >= 2) ? 1 : 0);
        }
        conv_block_kernel<<<NBATCH, 256, SMEM_BYTES>>>(
            pX + (size_t)nxt*NB,
            pZ + (size_t)cur*NB, pZ + (size_t)nxt*NB,
            pL + (size_t)cur*NB, pL + (size_t)nxt*NB,
            pZ + (size_t)nxt*NB, pL + (size_t)nxt*NB,
            out + (size_t)i*NB,
            out + (size_t)NLAYERS*NB + (size_t)i*NB,
            c1f, c2b, h, b1, b2, tzA, tLA, thr, i);
    }
}